// round 5
// baseline (speedup 1.0000x reference)
#include <cuda_runtime.h>
#include <math.h>

#define Bv 8
#define Cv 64
#define Hv 256
#define Wv 256
#define HWv 65536
#define BHW (Bv * HWv)
#define PI_F 3.14159265358979323846f

typedef unsigned long long u64;

// Scratch (device globals: allocation-free rule)
__device__ float2 g_dir[BHW];                 // (cos, sin) per pixel
__device__ float4 g_G4[(size_t)4 * BHW];      // [b][q][HW]; q0=tan h0-3, q1=tan h4-7, q2=nor h0-3, q3=nor h4-7
__device__ float  g_hid[(size_t)8 * BHW];     // relu'd hidden, plane-per-h layout

// ---- packed f32x2 helpers (Blackwell) ----
__device__ __forceinline__ u64 ffma2(u64 a, u64 b, u64 c) {
    u64 d;
    asm("fma.rn.f32x2 %0, %1, %2, %3;" : "=l"(d) : "l"(a), "l"(b), "l"(c));
    return d;
}
__device__ __forceinline__ u64 pack2(float lo, float hi) {
    u64 u; asm("mov.b64 %0, {%1, %2};" : "=l"(u) : "f"(lo), "f"(hi)); return u;
}
__device__ __forceinline__ float2 unpack2(u64 u) {
    float2 v; asm("mov.b64 {%0, %1}, %2;" : "=f"(v.x), "=f"(v.y) : "l"(u)); return v;
}
__device__ __forceinline__ float fsig(float z) {
    return __fdividef(1.f, 1.f + __expf(-z));
}

// ============================================================
// K1: theta = pi*sigmoid(w1 . relu(conv3x3(x,w3)+b3) + b1) -> (cos,sin)
// thread = 4 vertical pixels; hoisted offsets/predicates; unroll-2 channels
// ============================================================
__global__ __launch_bounds__(128) void k_theta(
    const float* __restrict__ x, const float* __restrict__ w3,
    const float* __restrict__ b3, const float* __restrict__ w1,
    const float* __restrict__ b1)
{
    __shared__ __align__(16) u64 sw2[Cv * 36];   // [c][tap][hp]
    int tid = threadIdx.y * 32 + threadIdx.x;
    for (int i = tid; i < Cv * 36; i += 128) {
        int c = i / 36, r = i % 36, tap = r >> 2, hp = r & 3;
        sw2[i] = pack2(w3[((2 * hp) * Cv + c) * 9 + tap],
                       w3[((2 * hp + 1) * Cv + c) * 9 + tap]);
    }
    __syncthreads();

    int xc = blockIdx.x * 32 + threadIdx.x;
    int y0 = blockIdx.y * 16 + threadIdx.y * 4;
    int b  = blockIdx.z;

    // hoist the 18 tap offsets + validity out of the channel loop
    int  offs[6][3];
    bool okm[6][3];
    #pragma unroll
    for (int r = 0; r < 6; r++) {
        int yy = y0 - 1 + r;
        bool yok = ((unsigned)yy < (unsigned)Hv);
        #pragma unroll
        for (int cc = 0; cc < 3; cc++) {
            int xx = xc - 1 + cc;
            bool v = yok && ((unsigned)xx < (unsigned)Wv);
            okm[r][cc]  = v;
            offs[r][cc] = v ? (yy * Wv + xx) : 0;
        }
    }

    u64 acc2[4][4];
    #pragma unroll
    for (int p = 0; p < 4; p++)
        #pragma unroll
        for (int hp = 0; hp < 4; hp++) acc2[p][hp] = 0ull;

    const float* xb = x + (size_t)b * Cv * HWv;
    #pragma unroll 2
    for (int c = 0; c < Cv; c++) {
        const float* xp = xb + c * HWv;
        float xv[6][3];
        #pragma unroll
        for (int r = 0; r < 6; r++)
            #pragma unroll
            for (int cc = 0; cc < 3; cc++)
                xv[r][cc] = okm[r][cc] ? __ldg(xp + offs[r][cc]) : 0.f;

        const u64* wc = sw2 + c * 36;
        #pragma unroll
        for (int ky = 0; ky < 3; ky++)
        #pragma unroll
        for (int kx = 0; kx < 3; kx++) {
            int tap = ky * 3 + kx;
            ulonglong2 wA = *reinterpret_cast<const ulonglong2*>(wc + tap * 4);
            ulonglong2 wB = *reinterpret_cast<const ulonglong2*>(wc + tap * 4 + 2);
            #pragma unroll
            for (int p = 0; p < 4; p++) {
                float v = xv[p + ky][kx];
                u64 vd = pack2(v, v);
                acc2[p][0] = ffma2(vd, wA.x, acc2[p][0]);
                acc2[p][1] = ffma2(vd, wA.y, acc2[p][1]);
                acc2[p][2] = ffma2(vd, wB.x, acc2[p][2]);
                acc2[p][3] = ffma2(vd, wB.y, acc2[p][3]);
            }
        }
    }

    float w1r[8], b3r[8];
    #pragma unroll
    for (int h = 0; h < 8; h++) { w1r[h] = __ldg(w1 + h); b3r[h] = __ldg(b3 + h); }
    float bias1 = __ldg(b1);
    #pragma unroll
    for (int p = 0; p < 4; p++) {
        float z = bias1;
        #pragma unroll
        for (int hp = 0; hp < 4; hp++) {
            float2 a = unpack2(acc2[p][hp]);
            z += w1r[2 * hp]     * fmaxf(a.x + b3r[2 * hp], 0.f);
            z += w1r[2 * hp + 1] * fmaxf(a.y + b3r[2 * hp + 1], 0.f);
        }
        float theta = PI_F * fsig(z);
        float s, cth; __sincosf(theta, &s, &cth);
        g_dir[(size_t)b * HWv + (size_t)(y0 + p) * Wv + xc] = make_float2(cth, s);
    }
}

// ============================================================
// K2: wr-projection of x: 64 -> 16 ch, stored as 4 float4 planes.
// thread = 2 HORIZONTAL pixels (LDG.64 in, STG.128 out)
// ============================================================
__global__ __launch_bounds__(256) void k_proj(
    const float* __restrict__ x, const float* __restrict__ wr)
{
    // [c][j] dup pairs: j<8 tan (wr[j][c]), j>=8 nor (wr[j-8][64+c])
    __shared__ __align__(16) u64 swr2[Cv * 16];
    int tid = threadIdx.x;
    for (int i = tid; i < Cv * 16; i += 256) {
        int c = i >> 4, j = i & 15;
        float w = (j < 8) ? wr[j * 128 + c] : wr[(j - 8) * 128 + 64 + c];
        swr2[i] = pack2(w, w);
    }
    __syncthreads();

    int g = blockIdx.x * 256 + tid;          // pixel-pair index
    size_t p0 = (size_t)g * 2;
    int b = (int)(p0 / HWv);
    size_t pin = p0 - (size_t)b * HWv;

    u64 acc2[16];                            // (px0, px1) per projected ch j
    #pragma unroll
    for (int j = 0; j < 16; j++) acc2[j] = 0ull;

    const float* xp = x + (size_t)b * Cv * HWv + pin;
    for (int c = 0; c < Cv; c++) {
        float2 v = __ldg(reinterpret_cast<const float2*>(xp + (size_t)c * HWv));
        u64 vp = pack2(v.x, v.y);
        const ulonglong2* wq = reinterpret_cast<const ulonglong2*>(swr2 + c * 16);
        #pragma unroll
        for (int q = 0; q < 8; q++) {
            ulonglong2 w = wq[q];
            acc2[2 * q]     = ffma2(vp, w.x, acc2[2 * q]);
            acc2[2 * q + 1] = ffma2(vp, w.y, acc2[2 * q + 1]);
        }
    }

    // q planes: q0=j0..3, q1=j4..7, q2=j8..11, q3=j12..15
    #pragma unroll
    for (int q = 0; q < 4; q++) {
        float2 a0 = unpack2(acc2[4 * q]);
        float2 a1 = unpack2(acc2[4 * q + 1]);
        float2 a2 = unpack2(acc2[4 * q + 2]);
        float2 a3 = unpack2(acc2[4 * q + 3]);
        size_t pb = ((size_t)b * 4 + q) * HWv + pin;
        g_G4[pb]     = make_float4(a0.x, a1.x, a2.x, a3.x);
        g_G4[pb + 1] = make_float4(a0.y, a1.y, a2.y, a3.y);
    }
}

// ============================================================
// K3: oriented pooling on G4 (18 taps x 4 corners x 2 LDG.128)
//     -> relu'd hidden written to plane-major scratch
// ============================================================
__device__ __forceinline__ void sample2q(const float4* __restrict__ P0,
                                         float cy, float cx, u64* hid)
{
    cy = fminf(fmaxf(cy, 0.f), (float)(Hv - 1));
    cx = fminf(fmaxf(cx, 0.f), (float)(Wv - 1));
    float y0f = floorf(cy), x0f = floorf(cx);
    float fy = cy - y0f, fx = cx - x0f;
    int iy0 = (int)y0f, ix0 = (int)x0f;
    int iy1 = min(iy0 + 1, Hv - 1), ix1 = min(ix0 + 1, Wv - 1);
    int o00 = iy0 * Wv + ix0, o01 = iy0 * Wv + ix1;
    int o10 = iy1 * Wv + ix0, o11 = iy1 * Wv + ix1;
    float w11 = fy * fx;
    float w10 = fy - w11, w01 = fx - w11, w00 = 1.f - fy - fx + w11;
    const float4* P1 = P0 + HWv;

    float4 a00 = __ldg(P0 + o00), b00 = __ldg(P1 + o00);
    float4 a01 = __ldg(P0 + o01), b01 = __ldg(P1 + o01);
    float4 a10 = __ldg(P0 + o10), b10 = __ldg(P1 + o10);
    float4 a11 = __ldg(P0 + o11), b11 = __ldg(P1 + o11);

    u64 W00 = pack2(w00, w00), W01 = pack2(w01, w01);
    u64 W10 = pack2(w10, w10), W11 = pack2(w11, w11);

    hid[0] = ffma2(pack2(a00.x, a00.y), W00, hid[0]);
    hid[1] = ffma2(pack2(a00.z, a00.w), W00, hid[1]);
    hid[2] = ffma2(pack2(b00.x, b00.y), W00, hid[2]);
    hid[3] = ffma2(pack2(b00.z, b00.w), W00, hid[3]);

    hid[0] = ffma2(pack2(a01.x, a01.y), W01, hid[0]);
    hid[1] = ffma2(pack2(a01.z, a01.w), W01, hid[1]);
    hid[2] = ffma2(pack2(b01.x, b01.y), W01, hid[2]);
    hid[3] = ffma2(pack2(b01.z, b01.w), W01, hid[3]);

    hid[0] = ffma2(pack2(a10.x, a10.y), W10, hid[0]);
    hid[1] = ffma2(pack2(a10.z, a10.w), W10, hid[1]);
    hid[2] = ffma2(pack2(b10.x, b10.y), W10, hid[2]);
    hid[3] = ffma2(pack2(b10.z, b10.w), W10, hid[3]);

    hid[0] = ffma2(pack2(a11.x, a11.y), W11, hid[0]);
    hid[1] = ffma2(pack2(a11.z, a11.w), W11, hid[1]);
    hid[2] = ffma2(pack2(b11.x, b11.y), W11, hid[2]);
    hid[3] = ffma2(pack2(b11.z, b11.w), W11, hid[3]);
}

__global__ __launch_bounds__(256) void k_pool(const float* __restrict__ br)
{
    __shared__ float sbr[8];
    int tid = threadIdx.x;
    if (tid < 8) sbr[tid] = br[tid];
    __syncthreads();

    int g = blockIdx.x * 256 + tid;
    int pix = g % HWv;
    int b   = g / HWv;
    int px = pix % Wv, py = pix / Wv;
    float2 dir = g_dir[g];
    float cs = dir.x, sn = dir.y;
    float fpx = (float)px, fpy = (float)py;

    u64 hid2[8];   // [0..3]=tan pairs (h01,h23,h45,h67), [4..7]=nor pairs
    #pragma unroll
    for (int i = 0; i < 8; i++) hid2[i] = 0ull;

    const float4* Gt = g_G4 + (size_t)b * 4 * HWv;        // q0 (q1 = +HWv)
    const float4* Gn = Gt + (size_t)2 * HWv;              // q2 (q3 = +HWv)
    #pragma unroll
    for (int ti = 0; ti < 9; ti++) {
        float t = (float)(ti - 4);
        sample2q(Gt, fpy + t * sn, fpx + t * cs, hid2);       // tangential
        sample2q(Gn, fpy + t * cs, fpx - t * sn, hid2 + 4);   // normal
    }

    #pragma unroll
    for (int h = 0; h < 8; h++) {
        float2 a  = unpack2(hid2[h >> 1]);
        float2 bn = unpack2(hid2[4 + (h >> 1)]);
        float vt = (h & 1) ? a.y : a.x;
        float vn = (h & 1) ? bn.y : bn.x;
        g_hid[(size_t)h * BHW + g] =
            fmaxf((vt + vn) * (1.f / 9.f) + sbr[h], 0.f);
    }
}

// ============================================================
// K4: gating — hidden -> we (8->128 packed over (c,c+64)) -> sigmoid-sum
//     -> alpha * x.  thread = 4 horizontal pixels; 3-MUFU sigmoid pair
// ============================================================
__global__ __launch_bounds__(256) void k_gate(
    const float* __restrict__ x, const float* __restrict__ we,
    const float* __restrict__ be, float* __restrict__ out)
{
    __shared__ __align__(16) u64 swe[512];   // [c][h] = {we[c][h], we[c+64][h]}
    __shared__ u64 sbe[64];
    int tid = threadIdx.x;
    for (int i = tid; i < 512; i += 256) {
        int c = i >> 3, h = i & 7;
        swe[i] = pack2(we[c * 8 + h], we[(c + 64) * 8 + h]);
    }
    if (tid < 64) sbe[tid] = pack2(be[tid], be[tid + 64]);
    __syncthreads();

    int g = blockIdx.x * 256 + tid;          // pixel-quad index
    size_t p0 = (size_t)g * 4;
    int b = g / (HWv / 4);

    u64 hdup[4][8];
    #pragma unroll
    for (int h = 0; h < 8; h++) {
        float4 hv = *reinterpret_cast<const float4*>(g_hid + (size_t)h * BHW + p0);
        hdup[0][h] = pack2(hv.x, hv.x);
        hdup[1][h] = pack2(hv.y, hv.y);
        hdup[2][h] = pack2(hv.z, hv.z);
        hdup[3][h] = pack2(hv.w, hv.w);
    }

    size_t pix_in_b = p0 - (size_t)b * HWv;
    size_t base = (size_t)b * Cv * HWv + pix_in_b;

    for (int c = 0; c < Cv; c++) {
        const ulonglong2* wq = reinterpret_cast<const ulonglong2*>(swe + c * 8);
        ulonglong2 wa = wq[0], wb = wq[1], wc2 = wq[2], wd = wq[3];
        u64 w[8] = {wa.x, wa.y, wb.x, wb.y, wc2.x, wc2.y, wd.x, wd.y};
        u64 bias = sbe[c];
        u64 z[4] = {bias, bias, bias, bias};
        #pragma unroll
        for (int h = 0; h < 8; h++) {
            #pragma unroll
            for (int p = 0; p < 4; p++)
                z[p] = ffma2(hdup[p][h], w[h], z[p]);
        }
        float4 xv = *reinterpret_cast<const float4*>(x + base + (size_t)c * HWv);
        float alpha[4];
        #pragma unroll
        for (int p = 0; p < 4; p++) {
            float2 zf = unpack2(z[p]);
            // sig(a)+sig(b) = (2 + ea + eb) / ((1+ea)(1+eb)),  e* = exp(-*)
            float ea = __expf(-zf.x);
            float eb = __expf(-zf.y);
            alpha[p] = __fdividef(2.f + ea + eb, (1.f + ea) * (1.f + eb));
        }
        float4 o = make_float4(alpha[0] * xv.x, alpha[1] * xv.y,
                               alpha[2] * xv.z, alpha[3] * xv.w);
        *reinterpret_cast<float4*>(out + base + (size_t)c * HWv) = o;
    }
}

// ============================================================
extern "C" void kernel_launch(void* const* d_in, const int* in_sizes, int n_in,
                              void* d_out, int out_size)
{
    const float* x  = (const float*)d_in[0];
    const float* w3 = (const float*)d_in[1];
    const float* b3 = (const float*)d_in[2];
    const float* w1 = (const float*)d_in[3];
    const float* b1 = (const float*)d_in[4];
    const float* wr = (const float*)d_in[5];
    const float* br = (const float*)d_in[6];
    const float* we = (const float*)d_in[7];
    const float* be = (const float*)d_in[8];
    float* out = (float*)d_out;

    dim3 gb1(Wv / 32, Hv / 16, Bv), tb1(32, 4);
    k_theta<<<gb1, tb1>>>(x, w3, b3, w1, b1);
    k_proj<<<(BHW / 2) / 256, 256>>>(x, wr);
    k_pool<<<BHW / 256, 256>>>(br);
    k_gate<<<(BHW / 4) / 256, 256>>>(x, we, be, out);
}

// round 6
// speedup vs baseline: 1.0035x; 1.0035x over previous
#include <cuda_runtime.h>
#include <math.h>

#define Bv 8
#define Cv 64
#define Hv 256
#define Wv 256
#define HWv 65536
#define BHW (Bv * HWv)
#define PI_F 3.14159265358979323846f

typedef unsigned long long u64;

// Scratch (device globals: allocation-free rule)
__device__ float2 g_dir[BHW];                 // (cos, sin) per pixel
__device__ float4 g_G4[(size_t)4 * BHW];      // [b][q][HW]; q0=tan h0-3, q1=tan h4-7, q2=nor h0-3, q3=nor h4-7
__device__ float  g_hid[(size_t)8 * BHW];     // relu'd hidden, plane-per-h layout

// ---- packed f32x2 helpers (Blackwell) ----
__device__ __forceinline__ u64 ffma2(u64 a, u64 b, u64 c) {
    u64 d;
    asm("fma.rn.f32x2 %0, %1, %2, %3;" : "=l"(d) : "l"(a), "l"(b), "l"(c));
    return d;
}
__device__ __forceinline__ u64 pack2(float lo, float hi) {
    u64 u; asm("mov.b64 %0, {%1, %2};" : "=l"(u) : "f"(lo), "f"(hi)); return u;
}
__device__ __forceinline__ float2 unpack2(u64 u) {
    float2 v; asm("mov.b64 {%0, %1}, %2;" : "=f"(v.x), "=f"(v.y) : "l"(u)); return v;
}
__device__ __forceinline__ float fsig(float z) {
    return __fdividef(1.f, 1.f + __expf(-z));
}

// ============================================================
// K1: theta = pi*sigmoid(w1 . relu(conv3x3(x,w3)+b3) + b1) -> (cos,sin)
// thread = 4 vertical pixels; hoisted offsets/predicates; unroll-2 channels
// ============================================================
__global__ __launch_bounds__(128) void k_theta(
    const float* __restrict__ x, const float* __restrict__ w3,
    const float* __restrict__ b3, const float* __restrict__ w1,
    const float* __restrict__ b1)
{
    __shared__ __align__(16) u64 sw2[Cv * 36];   // [c][tap][hp]
    int tid = threadIdx.y * 32 + threadIdx.x;
    for (int i = tid; i < Cv * 36; i += 128) {
        int c = i / 36, r = i % 36, tap = r >> 2, hp = r & 3;
        sw2[i] = pack2(w3[((2 * hp) * Cv + c) * 9 + tap],
                       w3[((2 * hp + 1) * Cv + c) * 9 + tap]);
    }
    __syncthreads();

    int xc = blockIdx.x * 32 + threadIdx.x;
    int y0 = blockIdx.y * 16 + threadIdx.y * 4;
    int b  = blockIdx.z;

    // hoist the 18 tap offsets + validity out of the channel loop
    int  offs[6][3];
    bool okm[6][3];
    #pragma unroll
    for (int r = 0; r < 6; r++) {
        int yy = y0 - 1 + r;
        bool yok = ((unsigned)yy < (unsigned)Hv);
        #pragma unroll
        for (int cc = 0; cc < 3; cc++) {
            int xx = xc - 1 + cc;
            bool v = yok && ((unsigned)xx < (unsigned)Wv);
            okm[r][cc]  = v;
            offs[r][cc] = v ? (yy * Wv + xx) : 0;
        }
    }

    u64 acc2[4][4];
    #pragma unroll
    for (int p = 0; p < 4; p++)
        #pragma unroll
        for (int hp = 0; hp < 4; hp++) acc2[p][hp] = 0ull;

    const float* xb = x + (size_t)b * Cv * HWv;
    #pragma unroll 2
    for (int c = 0; c < Cv; c++) {
        const float* xp = xb + c * HWv;
        float xv[6][3];
        #pragma unroll
        for (int r = 0; r < 6; r++)
            #pragma unroll
            for (int cc = 0; cc < 3; cc++)
                xv[r][cc] = okm[r][cc] ? __ldg(xp + offs[r][cc]) : 0.f;

        const u64* wc = sw2 + c * 36;
        #pragma unroll
        for (int ky = 0; ky < 3; ky++)
        #pragma unroll
        for (int kx = 0; kx < 3; kx++) {
            int tap = ky * 3 + kx;
            ulonglong2 wA = *reinterpret_cast<const ulonglong2*>(wc + tap * 4);
            ulonglong2 wB = *reinterpret_cast<const ulonglong2*>(wc + tap * 4 + 2);
            #pragma unroll
            for (int p = 0; p < 4; p++) {
                float v = xv[p + ky][kx];
                u64 vd = pack2(v, v);
                acc2[p][0] = ffma2(vd, wA.x, acc2[p][0]);
                acc2[p][1] = ffma2(vd, wA.y, acc2[p][1]);
                acc2[p][2] = ffma2(vd, wB.x, acc2[p][2]);
                acc2[p][3] = ffma2(vd, wB.y, acc2[p][3]);
            }
        }
    }

    float w1r[8], b3r[8];
    #pragma unroll
    for (int h = 0; h < 8; h++) { w1r[h] = __ldg(w1 + h); b3r[h] = __ldg(b3 + h); }
    float bias1 = __ldg(b1);
    #pragma unroll
    for (int p = 0; p < 4; p++) {
        float z = bias1;
        #pragma unroll
        for (int hp = 0; hp < 4; hp++) {
            float2 a = unpack2(acc2[p][hp]);
            z += w1r[2 * hp]     * fmaxf(a.x + b3r[2 * hp], 0.f);
            z += w1r[2 * hp + 1] * fmaxf(a.y + b3r[2 * hp + 1], 0.f);
        }
        float theta = PI_F * fsig(z);
        float s, cth; __sincosf(theta, &s, &cth);
        g_dir[(size_t)b * HWv + (size_t)(y0 + p) * Wv + xc] = make_float2(cth, s);
    }
}

// ============================================================
// K2: wr-projection of x: 64 -> 16 ch, stored as 4 float4 planes.
// thread = 2 HORIZONTAL pixels (LDG.64 in, STG.128 out)
// ============================================================
__global__ __launch_bounds__(256) void k_proj(
    const float* __restrict__ x, const float* __restrict__ wr)
{
    // [c][j] dup pairs: j<8 tan (wr[j][c]), j>=8 nor (wr[j-8][64+c])
    __shared__ __align__(16) u64 swr2[Cv * 16];
    int tid = threadIdx.x;
    for (int i = tid; i < Cv * 16; i += 256) {
        int c = i >> 4, j = i & 15;
        float w = (j < 8) ? wr[j * 128 + c] : wr[(j - 8) * 128 + 64 + c];
        swr2[i] = pack2(w, w);
    }
    __syncthreads();

    int g = blockIdx.x * 256 + tid;          // pixel-pair index
    size_t p0 = (size_t)g * 2;
    int b = (int)(p0 / HWv);
    size_t pin = p0 - (size_t)b * HWv;

    u64 acc2[16];                            // (px0, px1) per projected ch j
    #pragma unroll
    for (int j = 0; j < 16; j++) acc2[j] = 0ull;

    const float* xp = x + (size_t)b * Cv * HWv + pin;
    for (int c = 0; c < Cv; c++) {
        float2 v = __ldg(reinterpret_cast<const float2*>(xp + (size_t)c * HWv));
        u64 vp = pack2(v.x, v.y);
        const ulonglong2* wq = reinterpret_cast<const ulonglong2*>(swr2 + c * 16);
        #pragma unroll
        for (int q = 0; q < 8; q++) {
            ulonglong2 w = wq[q];
            acc2[2 * q]     = ffma2(vp, w.x, acc2[2 * q]);
            acc2[2 * q + 1] = ffma2(vp, w.y, acc2[2 * q + 1]);
        }
    }

    // q planes: q0=j0..3, q1=j4..7, q2=j8..11, q3=j12..15
    #pragma unroll
    for (int q = 0; q < 4; q++) {
        float2 a0 = unpack2(acc2[4 * q]);
        float2 a1 = unpack2(acc2[4 * q + 1]);
        float2 a2 = unpack2(acc2[4 * q + 2]);
        float2 a3 = unpack2(acc2[4 * q + 3]);
        size_t pb = ((size_t)b * 4 + q) * HWv + pin;
        g_G4[pb]     = make_float4(a0.x, a1.x, a2.x, a3.x);
        g_G4[pb + 1] = make_float4(a0.y, a1.y, a2.y, a3.y);
    }
}

// ============================================================
// K3: oriented pooling on G4 (18 taps x 4 corners x 2 LDG.128)
//     -> relu'd hidden written to plane-major scratch
// ============================================================
__device__ __forceinline__ void sample2q(const float4* __restrict__ P0,
                                         float cy, float cx, u64* hid)
{
    cy = fminf(fmaxf(cy, 0.f), (float)(Hv - 1));
    cx = fminf(fmaxf(cx, 0.f), (float)(Wv - 1));
    float y0f = floorf(cy), x0f = floorf(cx);
    float fy = cy - y0f, fx = cx - x0f;
    int iy0 = (int)y0f, ix0 = (int)x0f;
    int iy1 = min(iy0 + 1, Hv - 1), ix1 = min(ix0 + 1, Wv - 1);
    int o00 = iy0 * Wv + ix0, o01 = iy0 * Wv + ix1;
    int o10 = iy1 * Wv + ix0, o11 = iy1 * Wv + ix1;
    float w11 = fy * fx;
    float w10 = fy - w11, w01 = fx - w11, w00 = 1.f - fy - fx + w11;
    const float4* P1 = P0 + HWv;

    float4 a00 = __ldg(P0 + o00), b00 = __ldg(P1 + o00);
    float4 a01 = __ldg(P0 + o01), b01 = __ldg(P1 + o01);
    float4 a10 = __ldg(P0 + o10), b10 = __ldg(P1 + o10);
    float4 a11 = __ldg(P0 + o11), b11 = __ldg(P1 + o11);

    u64 W00 = pack2(w00, w00), W01 = pack2(w01, w01);
    u64 W10 = pack2(w10, w10), W11 = pack2(w11, w11);

    hid[0] = ffma2(pack2(a00.x, a00.y), W00, hid[0]);
    hid[1] = ffma2(pack2(a00.z, a00.w), W00, hid[1]);
    hid[2] = ffma2(pack2(b00.x, b00.y), W00, hid[2]);
    hid[3] = ffma2(pack2(b00.z, b00.w), W00, hid[3]);

    hid[0] = ffma2(pack2(a01.x, a01.y), W01, hid[0]);
    hid[1] = ffma2(pack2(a01.z, a01.w), W01, hid[1]);
    hid[2] = ffma2(pack2(b01.x, b01.y), W01, hid[2]);
    hid[3] = ffma2(pack2(b01.z, b01.w), W01, hid[3]);

    hid[0] = ffma2(pack2(a10.x, a10.y), W10, hid[0]);
    hid[1] = ffma2(pack2(a10.z, a10.w), W10, hid[1]);
    hid[2] = ffma2(pack2(b10.x, b10.y), W10, hid[2]);
    hid[3] = ffma2(pack2(b10.z, b10.w), W10, hid[3]);

    hid[0] = ffma2(pack2(a11.x, a11.y), W11, hid[0]);
    hid[1] = ffma2(pack2(a11.z, a11.w), W11, hid[1]);
    hid[2] = ffma2(pack2(b11.x, b11.y), W11, hid[2]);
    hid[3] = ffma2(pack2(b11.z, b11.w), W11, hid[3]);
}

__global__ __launch_bounds__(256) void k_pool(const float* __restrict__ br)
{
    __shared__ float sbr[8];
    int tid = threadIdx.x;
    if (tid < 8) sbr[tid] = br[tid];
    __syncthreads();

    int g = blockIdx.x * 256 + tid;
    int pix = g % HWv;
    int b   = g / HWv;
    int px = pix % Wv, py = pix / Wv;
    float2 dir = g_dir[g];
    float cs = dir.x, sn = dir.y;
    float fpx = (float)px, fpy = (float)py;

    u64 hid2[8];   // [0..3]=tan pairs (h01,h23,h45,h67), [4..7]=nor pairs
    #pragma unroll
    for (int i = 0; i < 8; i++) hid2[i] = 0ull;

    const float4* Gt = g_G4 + (size_t)b * 4 * HWv;        // q0 (q1 = +HWv)
    const float4* Gn = Gt + (size_t)2 * HWv;              // q2 (q3 = +HWv)
    #pragma unroll
    for (int ti = 0; ti < 9; ti++) {
        float t = (float)(ti - 4);
        sample2q(Gt, fpy + t * sn, fpx + t * cs, hid2);       // tangential
        sample2q(Gn, fpy + t * cs, fpx - t * sn, hid2 + 4);   // normal
    }

    #pragma unroll
    for (int h = 0; h < 8; h++) {
        float2 a  = unpack2(hid2[h >> 1]);
        float2 bn = unpack2(hid2[4 + (h >> 1)]);
        float vt = (h & 1) ? a.y : a.x;
        float vn = (h & 1) ? bn.y : bn.x;
        g_hid[(size_t)h * BHW + g] =
            fmaxf((vt + vn) * (1.f / 9.f) + sbr[h], 0.f);
    }
}

// ============================================================
// K4: gating — hidden -> we (8->128 packed over (c,c+64)) -> sigmoid-sum
//     -> alpha * x.  thread = 4 horizontal pixels; 3-MUFU sigmoid pair
// ============================================================
__global__ __launch_bounds__(256) void k_gate(
    const float* __restrict__ x, const float* __restrict__ we,
    const float* __restrict__ be, float* __restrict__ out)
{
    __shared__ __align__(16) u64 swe[512];   // [c][h] = {we[c][h], we[c+64][h]}
    __shared__ u64 sbe[64];
    int tid = threadIdx.x;
    for (int i = tid; i < 512; i += 256) {
        int c = i >> 3, h = i & 7;
        swe[i] = pack2(we[c * 8 + h], we[(c + 64) * 8 + h]);
    }
    if (tid < 64) sbe[tid] = pack2(be[tid], be[tid + 64]);
    __syncthreads();

    int g = blockIdx.x * 256 + tid;          // pixel-quad index
    size_t p0 = (size_t)g * 4;
    int b = g / (HWv / 4);

    u64 hdup[4][8];
    #pragma unroll
    for (int h = 0; h < 8; h++) {
        float4 hv = *reinterpret_cast<const float4*>(g_hid + (size_t)h * BHW + p0);
        hdup[0][h] = pack2(hv.x, hv.x);
        hdup[1][h] = pack2(hv.y, hv.y);
        hdup[2][h] = pack2(hv.z, hv.z);
        hdup[3][h] = pack2(hv.w, hv.w);
    }

    size_t pix_in_b = p0 - (size_t)b * HWv;
    size_t base = (size_t)b * Cv * HWv + pix_in_b;

    for (int c = 0; c < Cv; c++) {
        const ulonglong2* wq = reinterpret_cast<const ulonglong2*>(swe + c * 8);
        ulonglong2 wa = wq[0], wb = wq[1], wc2 = wq[2], wd = wq[3];
        u64 w[8] = {wa.x, wa.y, wb.x, wb.y, wc2.x, wc2.y, wd.x, wd.y};
        u64 bias = sbe[c];
        u64 z[4] = {bias, bias, bias, bias};
        #pragma unroll
        for (int h = 0; h < 8; h++) {
            #pragma unroll
            for (int p = 0; p < 4; p++)
                z[p] = ffma2(hdup[p][h], w[h], z[p]);
        }
        float4 xv = *reinterpret_cast<const float4*>(x + base + (size_t)c * HWv);
        float alpha[4];
        #pragma unroll
        for (int p = 0; p < 4; p++) {
            float2 zf = unpack2(z[p]);
            // sig(a)+sig(b) = (2 + ea + eb) / ((1+ea)(1+eb)),  e* = exp(-*)
            float ea = __expf(-zf.x);
            float eb = __expf(-zf.y);
            alpha[p] = __fdividef(2.f + ea + eb, (1.f + ea) * (1.f + eb));
        }
        float4 o = make_float4(alpha[0] * xv.x, alpha[1] * xv.y,
                               alpha[2] * xv.z, alpha[3] * xv.w);
        *reinterpret_cast<float4*>(out + base + (size_t)c * HWv) = o;
    }
}

// ============================================================
extern "C" void kernel_launch(void* const* d_in, const int* in_sizes, int n_in,
                              void* d_out, int out_size)
{
    const float* x  = (const float*)d_in[0];
    const float* w3 = (const float*)d_in[1];
    const float* b3 = (const float*)d_in[2];
    const float* w1 = (const float*)d_in[3];
    const float* b1 = (const float*)d_in[4];
    const float* wr = (const float*)d_in[5];
    const float* br = (const float*)d_in[6];
    const float* we = (const float*)d_in[7];
    const float* be = (const float*)d_in[8];
    float* out = (float*)d_out;

    dim3 gb1(Wv / 32, Hv / 16, Bv), tb1(32, 4);
    k_theta<<<gb1, tb1>>>(x, w3, b3, w1, b1);
    k_proj<<<(BHW / 2) / 256, 256>>>(x, wr);
    k_pool<<<BHW / 256, 256>>>(br);
    k_gate<<<(BHW / 4) / 256, 256>>>(x, we, be, out);
}